// round 14
// baseline (speedup 1.0000x reference)
#include <cuda_runtime.h>
#include <math.h>
#include <stdint.h>

#define HH    64
#define DIMC  512     // per-axis sinusoid width
#define ODIM  256     // output dim
#define BATCH 8
#define NKC   8       // K-chunks per half (64 k each) == cluster size

// Fully overwritten every launch -> stateless (no zeroing, no atomics).
__device__ float g_Cpart[NKC][2 * HH][ODIM];   // 1 MB partials
__device__ float g_C[2 * HH][ODIM];            // reduced C (128 KB)

// ---------------------------------------------------------------------------
// k1: cluster-fused embed + split-K GEMM + in-cluster reduction.
// grid (8 kc, 8 nt, 2 half) = 128 CTAs, cluster (8,1,1) along kc.
// CTA (kc,nt,half): partial[kc] over k in [kc*64,kc*64+64) for tile
// (M=64, N=32 at n0=nt*32). After HW cluster barrier, CTA kc reduces rows
// [kc*8, kc*8+8) of the tile across all 8 partials into g_C (plain stores).
// ---------------------------------------------------------------------------
__global__ __launch_bounds__(256) __cluster_dims__(NKC, 1, 1)
void k1_gemm_cluster(const float* __restrict__ W) {
    const int kc   = blockIdx.x;          // 0..7  (cluster rank)
    const int nt   = blockIdx.y;          // 0..7
    const int half = blockIdx.z;          // 0..1
    const int k0   = kc * 64;
    const int n0   = nt * 32;
    const int off  = half * DIMC;

    __shared__ float fr[64];
    __shared__ float Et[64][66];   // [k][m], 8B-aligned float2 rows
    __shared__ float Ws[64][36];   // [k][n], 16B-aligned float4 rows

    const int t = threadIdx.x;

    if (t < 64) {
        int c = k0 + t;
        float expo = (c < 256) ? (float)(2 * c + 1) * (1.0f / 512.0f)
                               : (float)(2 * (c - 256)) * (1.0f / 512.0f);
        fr[t] = __expf(-expo * 6.907755278982137f);   // 1000^(-expo)
    }
    __syncthreads();

    // embed tile: Et[kk][m] = embed(m)[k0+kk]  (4096 sin/cos, 16 per thread)
    #pragma unroll
    for (int e = t; e < 64 * 64; e += 256) {
        int m = e & 63, kk = e >> 6;
        float zf = (float)m * fr[kk];
        Et[kk][m] = (k0 + kk < 256) ? __sinf(zf) : __cosf(zf);
    }
    // W tile (transposed): rows n0..n0+31, cols k0..k0+63, coalesced over k
    #pragma unroll
    for (int e = t; e < 32 * 64; e += 256) {
        int kk = e & 63, i = e >> 6;
        Ws[kk][i] = W[(size_t)(n0 + i) * (2 * DIMC) + off + k0 + kk];
    }
    __syncthreads();

    const int tx = t & 7, ty = t >> 3;    // 8 x 32 threads
    const int mb = ty * 2, nb = tx * 4;   // 2x4 micro-tile

    float acc[2][4] = {};
    #pragma unroll 8
    for (int k = 0; k < 64; k++) {
        float2 a = *(const float2*)&Et[k][mb];
        float4 b = *(const float4*)&Ws[k][nb];
        acc[0][0] += a.x * b.x; acc[0][1] += a.x * b.y; acc[0][2] += a.x * b.z; acc[0][3] += a.x * b.w;
        acc[1][0] += a.y * b.x; acc[1][1] += a.y * b.y; acc[1][2] += a.y * b.z; acc[1][3] += a.y * b.w;
    }

    // store partial (plain, disjoint)
    const int rbase = half * 64 + mb;
    #pragma unroll
    for (int i = 0; i < 2; i++) {
        float4 v = make_float4(acc[i][0], acc[i][1], acc[i][2], acc[i][3]);
        *(float4*)&g_Cpart[kc][rbase + i][n0 + nb] = v;
    }

    // make partials visible cluster-wide, then HW cluster barrier
    __threadfence();
    asm volatile("barrier.cluster.arrive.aligned;" ::: "memory");
    asm volatile("barrier.cluster.wait.aligned;"   ::: "memory");

    // reduce: CTA kc owns rows [kc*8, kc*8+8) of this (nt,half) tile.
    // 8 rows x 32 cols = 256 elems, one per thread; coalesced over cols.
    {
        int row  = half * 64 + kc * 8 + (t >> 5);   // t>>5 in 0..7
        int col  = n0 + (t & 31);
        float s = 0.f;
        #pragma unroll
        for (int p = 0; p < NKC; p++)
            s += g_Cpart[p][row][col];
        g_C[row][col] = s;
    }
}

// ---------------------------------------------------------------------------
// k2: broadcast write, read-amortized, stateless (measured ~7.0us).
//   out[b][h][w][o] = C[h][o] + C[64+w][o]
// block (h, wq): w in [wq*16, wq*16+16), all 8 batches. grid (64,4) x 256 thr.
// ---------------------------------------------------------------------------
__global__ __launch_bounds__(256) void k2_write(float* __restrict__ out) {
    const int t  = threadIdx.x;
    const int q  = t & 63;        // float4 column (o = 4q)
    const int rg = t >> 6;        // 0..3 -> 4 w-rows each
    const int h  = blockIdx.x;    // 0..63
    const int wq = blockIdx.y;    // 0..3

    const size_t colo = (size_t)q * 4;
    float4 a = *(const float4*)&g_C[h][colo];

    #pragma unroll
    for (int i = 0; i < 4; i++) {
        int w = wq * 16 + rg * 4 + i;
        float4 e = *(const float4*)&g_C[64 + w][colo];
        float4 v;
        v.x = a.x + e.x; v.y = a.y + e.y; v.z = a.z + e.z; v.w = a.w + e.w;

        size_t base = (((size_t)h * HH + w) * ODIM) + colo;
        const size_t bstride = (size_t)HH * HH * ODIM;
        #pragma unroll
        for (int b = 0; b < BATCH; b++)
            *(float4*)&out[base + (size_t)b * bstride] = v;
    }
}

// ---------------------------------------------------------------------------
extern "C" void kernel_launch(void* const* d_in, const int* in_sizes, int n_in,
                              void* d_out, int out_size) {
    const float* W = (const float*)d_in[0];   // W_im: (256, 1024) fp32
    float* out = (float*)d_out;               // (8, 64, 64, 256, 1) fp32

    dim3 g1(NKC, 8, 2);
    k1_gemm_cluster<<<g1, 256>>>(W);
    dim3 g2(HH, 4);
    k2_write<<<g2, 256>>>(out);
}

// round 15
// speedup vs baseline: 1.1555x; 1.1555x over previous
#include <cuda_runtime.h>
#include <math.h>
#include <stdint.h>

#define HH    64
#define DIMC  512     // per-axis sinusoid width
#define ODIM  256     // output dim
#define BATCH 8
#define NSPLIT 16     // split-K partials

// Partial sums: g_Cpart[kc][r][o]; r<64 -> A-half (W cols 0:512), r>=64 -> B-half.
// Plain overwrite stores every launch -> no zeroing, no atomics, no state.
__device__ float g_Cpart[NSPLIT][2 * HH][ODIM];   // 2 MB
__device__ float g_C[2 * HH][ODIM];               // reduced result (128 KB)

// ---------------------------------------------------------------------------
// k1: fused embed + split-K GEMM partials (plain stores) — R7 verbatim
// (measured 6.24us as first kernel incl. graph-start ramp).
// grid (16 kc, 4 ntiles, 2 halves) = 128 blocks x 256 threads.
// ---------------------------------------------------------------------------
__global__ __launch_bounds__(256) void k1_embed_gemm(const float* __restrict__ W) {
    const int kc   = blockIdx.x;
    const int k0   = kc * 32;
    const int n0   = blockIdx.y * 64;
    const int half = blockIdx.z;
    const int off  = half * DIMC;

    __shared__ float fr[32];
    __shared__ float Es[64][36];
    __shared__ float Ws[32][68];

    const int t = threadIdx.x;

    if (t < 32) {
        int c = k0 + t;
        float expo = (c < 256) ? (float)(2 * c + 1) * (1.0f / 512.0f)
                               : (float)(2 * (c - 256)) * (1.0f / 512.0f);
        fr[t] = __expf(-expo * 6.907755278982137f);   // 1000^(-expo)
    }
    __syncthreads();

    #pragma unroll
    for (int e = t; e < 64 * 32; e += 256) {
        int kk = e & 31, m = e >> 5;
        float zf = (float)m * fr[kk];
        Es[m][kk] = (k0 + kk < 256) ? __sinf(zf) : __cosf(zf);
    }
    #pragma unroll
    for (int e = t; e < 64 * 32; e += 256) {
        int kk = e & 31, i = e >> 5;
        Ws[kk][i] = W[(size_t)(n0 + i) * (2 * DIMC) + off + k0 + kk];
    }
    __syncthreads();

    const int tx = t & 15, ty = t >> 4;
    const int mb = ty * 4, nb = tx * 4;

    float acc[4][4] = {};
    #pragma unroll 8
    for (int k = 0; k < 32; k++) {
        float4 b = *(const float4*)&Ws[k][nb];
        float a0 = Es[mb + 0][k];
        float a1 = Es[mb + 1][k];
        float a2 = Es[mb + 2][k];
        float a3 = Es[mb + 3][k];
        acc[0][0] += a0 * b.x; acc[0][1] += a0 * b.y; acc[0][2] += a0 * b.z; acc[0][3] += a0 * b.w;
        acc[1][0] += a1 * b.x; acc[1][1] += a1 * b.y; acc[1][2] += a1 * b.z; acc[1][3] += a1 * b.w;
        acc[2][0] += a2 * b.x; acc[2][1] += a2 * b.y; acc[2][2] += a2 * b.z; acc[2][3] += a2 * b.w;
        acc[3][0] += a3 * b.x; acc[3][1] += a3 * b.y; acc[3][2] += a3 * b.z; acc[3][3] += a3 * b.w;
    }

    const int rbase = half * 64 + mb;
    #pragma unroll
    for (int i = 0; i < 4; i++) {
        float4 v = make_float4(acc[i][0], acc[i][1], acc[i][2], acc[i][3]);
        *(float4*)&g_Cpart[kc][rbase + i][n0 + nb] = v;
    }
}

// ---------------------------------------------------------------------------
// k1b: reduce 16 partials -> g_C (R7 verbatim). 64 blocks x 128 threads.
// ---------------------------------------------------------------------------
__global__ __launch_bounds__(128) void k1b_reduce() {
    const int idx = blockIdx.x * 128 + threadIdx.x;     // 0..8191 float4 slots
    const float4* p = (const float4*)g_Cpart;
    const int stride = (2 * HH * ODIM) / 4;             // 8192 float4 per partial

    float4 s = p[idx];
    #pragma unroll
    for (int k = 1; k < NSPLIT; k++) {
        float4 v = p[idx + k * stride];
        s.x += v.x; s.y += v.y; s.z += v.z; s.w += v.w;
    }
    ((float4*)g_C)[idx] = s;
}

// ---------------------------------------------------------------------------
// k2: broadcast write — MORE CONCURRENCY (fix for R14's latency-bound profile).
//   out[b][h][w][o] = C[h][o] + C[64+w][o]
// grid (64, 8) = 512 blocks x 256 threads; block (h, wg) covers 8 w-rows,
// all 8 batches. Per thread: 2 w-rows -> 16 independent STG.128.
// Reads ~9 KB C/block (4.6 MB total); writes 33.5 MB coalesced.
// ---------------------------------------------------------------------------
__global__ __launch_bounds__(256) void k2_write(float* __restrict__ out) {
    const int t  = threadIdx.x;
    const int q  = t & 63;        // float4 column (o = 4q)
    const int rg = t >> 6;        // 0..3 -> 2 w-rows each
    const int h  = blockIdx.x;    // 0..63
    const int wg = blockIdx.y;    // 0..7

    const size_t colo = (size_t)q * 4;
    const size_t bstride = (size_t)HH * HH * ODIM;   // per-batch stride
    float4 a = *(const float4*)&g_C[h][colo];

    const int w0 = wg * 8 + rg * 2;
    const int w1 = w0 + 1;

    float4 e0 = *(const float4*)&g_C[64 + w0][colo];
    float4 e1 = *(const float4*)&g_C[64 + w1][colo];

    float4 v0, v1;
    v0.x = a.x + e0.x; v0.y = a.y + e0.y; v0.z = a.z + e0.z; v0.w = a.w + e0.w;
    v1.x = a.x + e1.x; v1.y = a.y + e1.y; v1.z = a.z + e1.z; v1.w = a.w + e1.w;

    size_t base0 = (((size_t)h * HH + w0) * ODIM) + colo;
    size_t base1 = (((size_t)h * HH + w1) * ODIM) + colo;

    // interleave the two rows across batches: 16 independent STG.128
    #pragma unroll
    for (int b = 0; b < BATCH; b++) {
        size_t bo = (size_t)b * bstride;
        *(float4*)&out[base0 + bo] = v0;
        *(float4*)&out[base1 + bo] = v1;
    }
}

// ---------------------------------------------------------------------------
extern "C" void kernel_launch(void* const* d_in, const int* in_sizes, int n_in,
                              void* d_out, int out_size) {
    const float* W = (const float*)d_in[0];   // W_im: (256, 1024) fp32
    float* out = (float*)d_out;               // (8, 64, 64, 256, 1) fp32

    dim3 g1(NSPLIT, 4, 2);
    k1_embed_gemm<<<g1, 256>>>(W);
    k1b_reduce<<<64, 128>>>();
    dim3 g2(HH, 8);
    k2_write<<<g2, 256>>>(out);
}